// round 2
// baseline (speedup 1.0000x reference)
#include <cuda_runtime.h>
#include <cstdint>

#define NT      9
#define SEQ     512
#define BATCH   64
#define EMB     1024
#define CHUNKS  8
#define CHUNK_LEN 64

#define L2E 1.4426950408889634f
#define LN2 0.6931471805599453f

// scratch: per-(batch,chunk) 9x9 semiring matrix products
__device__ float g_M[BATCH * CHUNKS * 81];
// tags dtype flag: 1 = int64, 0 = int32
__device__ int   g_tags64;

__device__ __forceinline__ void ffma2(unsigned long long& acc,
                                      unsigned long long a,
                                      unsigned long long b)
{
    asm("fma.rn.f32x2 %0, %1, %2, %3;" : "=l"(acc) : "l"(a), "l"(b), "l"(acc));
}
__device__ __forceinline__ float fast_ex2(float x)
{
    float r; asm("ex2.approx.ftz.f32 %0, %1;" : "=f"(r) : "f"(x)); return r;
}
__device__ __forceinline__ float fast_lg2(float x)
{
    float r; asm("lg2.approx.ftz.f32 %0, %1;" : "=f"(r) : "f"(x)); return r;
}

// ---------------------------------------------------------------------------
// Kernel 1: emission = log_softmax(embed @ W^T + b)
// 512 blocks x 256 threads; block = 64 rows x 4 K-quarters (256 floats each).
// W in smem, pair-interleaved for packed f32x2 FMA. Warp = 32 rows at the same
// K-quarter -> all smem W reads are broadcasts.
// ---------------------------------------------------------------------------
__global__ __launch_bounds__(256, 4) void emis2(
    const float* __restrict__ embed,
    const float* __restrict__ W,
    const float* __restrict__ bias,
    const unsigned* __restrict__ tags_words,
    float* __restrict__ out)
{
    __shared__ float sWp[8 * EMB];   // [e][t0..t7] interleaved, 32 KB
    __shared__ float sW8[EMB];       // t=8 column, 4 KB
    __shared__ float red[64 * 36];   // [r][q][9] partial sums, 9 KB

    const int tid = threadIdx.x;

    if (blockIdx.x == 0) {
        // tags dtype detection: if int64 (values 0..8), every odd 32-bit word is 0.
        __shared__ int s_any;
        if (tid == 0) s_any = 0;
        __syncthreads();
        int nz = 0;
        for (int q = tid; q < 2048; q += 256)
            nz |= (tags_words[2 * q + 1] != 0u);
        if (nz) atomicOr(&s_any, 1);
        __syncthreads();
        if (tid == 0) {
            g_tags64 = s_any ? 0 : 1;
            out[0] = 0.0f;               // ll accumulator
        }
    }

    // load W into smem (pair-interleaved)
    for (int idx = tid; idx < NT * EMB; idx += 256) {
        int t = idx >> 10;
        int e = idx & 1023;
        float w = W[idx];
        if (t < 8) sWp[e * 8 + t] = w;
        else       sW8[e] = w;
    }
    __syncthreads();

    const int q   = tid >> 6;        // K-quarter 0..3
    const int r   = tid & 63;        // row within block
    const int row = blockIdx.x * 64 + r;

    const float* eb = embed + (size_t)row * EMB + q * 256;
    const float* wp = sWp + q * 256 * 8;
    const float* w8 = sW8 + q * 256;

    unsigned long long a01 = 0ull, a23 = 0ull, a45 = 0ull, a67 = 0ull;
    float a8 = 0.0f;

#pragma unroll 8
    for (int e = 0; e < 256; e += 4) {
        float4 x   = *(const float4*)(eb + e);
        float4 w8v = *(const float4*)(w8 + e);

        {
            unsigned long long xx;
            asm("mov.b64 %0, {%1,%1};" : "=l"(xx) : "f"(x.x));
            ulonglong2 wA = *(const ulonglong2*)(wp + (e + 0) * 8);
            ulonglong2 wB = *(const ulonglong2*)(wp + (e + 0) * 8 + 4);
            ffma2(a01, xx, wA.x); ffma2(a23, xx, wA.y);
            ffma2(a45, xx, wB.x); ffma2(a67, xx, wB.y);
            a8 = fmaf(x.x, w8v.x, a8);
        }
        {
            unsigned long long xx;
            asm("mov.b64 %0, {%1,%1};" : "=l"(xx) : "f"(x.y));
            ulonglong2 wA = *(const ulonglong2*)(wp + (e + 1) * 8);
            ulonglong2 wB = *(const ulonglong2*)(wp + (e + 1) * 8 + 4);
            ffma2(a01, xx, wA.x); ffma2(a23, xx, wA.y);
            ffma2(a45, xx, wB.x); ffma2(a67, xx, wB.y);
            a8 = fmaf(x.y, w8v.y, a8);
        }
        {
            unsigned long long xx;
            asm("mov.b64 %0, {%1,%1};" : "=l"(xx) : "f"(x.z));
            ulonglong2 wA = *(const ulonglong2*)(wp + (e + 2) * 8);
            ulonglong2 wB = *(const ulonglong2*)(wp + (e + 2) * 8 + 4);
            ffma2(a01, xx, wA.x); ffma2(a23, xx, wA.y);
            ffma2(a45, xx, wB.x); ffma2(a67, xx, wB.y);
            a8 = fmaf(x.z, w8v.z, a8);
        }
        {
            unsigned long long xx;
            asm("mov.b64 %0, {%1,%1};" : "=l"(xx) : "f"(x.w));
            ulonglong2 wA = *(const ulonglong2*)(wp + (e + 3) * 8);
            ulonglong2 wB = *(const ulonglong2*)(wp + (e + 3) * 8 + 4);
            ffma2(a01, xx, wA.x); ffma2(a23, xx, wA.y);
            ffma2(a45, xx, wB.x); ffma2(a67, xx, wB.y);
            a8 = fmaf(x.w, w8v.w, a8);
        }
    }

    // write partials [r][q][0..8]
    {
        float2 f01 = *(float2*)&a01;
        float2 f23 = *(float2*)&a23;
        float2 f45 = *(float2*)&a45;
        float2 f67 = *(float2*)&a67;
        float* rp = &red[r * 36 + q * 9];
        rp[0] = f01.x; rp[1] = f01.y;
        rp[2] = f23.x; rp[3] = f23.y;
        rp[4] = f45.x; rp[5] = f45.y;
        rp[6] = f67.x; rp[7] = f67.y;
        rp[8] = a8;
    }
    __syncthreads();

    // reduction + log_softmax + store (threads 0..63 = one row each)
    if (tid < 64) {
        const float* rp = &red[tid * 36];
        float acc[NT];
#pragma unroll
        for (int t = 0; t < NT; t++)
            acc[t] = rp[t] + rp[9 + t] + rp[18 + t] + rp[27 + t] + bias[t];

        float mx = acc[0];
#pragma unroll
        for (int t = 1; t < NT; t++) mx = fmaxf(mx, acc[t]);
        float s = 0.0f;
#pragma unroll
        for (int t = 0; t < NT; t++) s += fast_ex2((acc[t] - mx) * L2E);
        float lse = fmaf(fast_lg2(s), LN2, mx);

        float* o = out + 1 + (size_t)(blockIdx.x * 64 + tid) * NT;
#pragma unroll
        for (int t = 0; t < NT; t++) o[t] = acc[t] - lse;
    }
}

// ---------------------------------------------------------------------------
// Kernel 2: chunked forward scan. Row i of the running log-semiring matrix
// product depends only on row i -> independent 9-lane row-scans, no smem,
// no syncthreads. exp(trans) factorization: lse_k(v_k + T[k][j]) =
// r + LN2*log2( sum_k 2^{(v_k - r)*L2E} * E2[k][j] ),  E2 = 2^{T*L2E}.
// block = 96 threads = 3 warps, warp handles 3 rows of one (b,chunk).
// ---------------------------------------------------------------------------
__global__ __launch_bounds__(96) void crf_chunks2(
    const float* __restrict__ outbuf,   // d_out; emission at +1
    const int*   __restrict__ mask,
    const float* __restrict__ trans)
{
    const float* emis = outbuf + 1;
    const int c = blockIdx.x, b = blockIdx.y;
    const int w    = threadIdx.x >> 5;
    const int lane = threadIdx.x & 31;

    int g = lane / 9; if (g > 2) g = 2;          // lanes 27..31 mirror group 2
    const int j = lane % 9;
    const int i = w * 3 + g;
    const int rowbase = g * 9;

    float E2[9];
#pragma unroll
    for (int k = 0; k < 9; k++) E2[k] = fast_ex2(trans[k * 9 + j] * L2E);
    const float tij = trans[i * 9 + j];

    float v = (j == i) ? 0.0f : -1e30f;          // identity row
    bool started = false;

    const int t0 = 1 + c * CHUNK_LEN;
    const int t1 = min(SEQ, t0 + CHUNK_LEN);
    const float* em_b = emis + (size_t)b * SEQ * NT;
    const int*   mk   = mask + b * SEQ;

    int   m_nxt  = mk[t0];
    float ev_nxt = em_b[t0 * NT + j];

    for (int t = t0; t < t1; ++t) {
        const int   m  = m_nxt;
        const float ev = ev_nxt;
        if (t + 1 < t1) {
            m_nxt  = mk[t + 1];
            ev_nxt = em_b[(t + 1) * NT + j];
        }
        if (m) {
            if (!started) {
                v = tij + ev;                    // M = A_t on first active step
                started = true;
            } else {
                float r = __shfl_sync(0xffffffffu, v, rowbase);
                float e = fast_ex2((v - r) * L2E);
                float s = 0.0f;
#pragma unroll
                for (int k = 0; k < 9; k++)
                    s = fmaf(__shfl_sync(0xffffffffu, e, rowbase + k), E2[k], s);
                v = fmaf(fast_lg2(s), LN2, r) + ev;
            }
        }
    }

    if (lane < 27) g_M[(b * CHUNKS + c) * 81 + i * 9 + j] = v;
}

// ---------------------------------------------------------------------------
// Kernel 3: per-batch numerator + chunk-combine + denominator + atomicAdd ll.
// ---------------------------------------------------------------------------
__global__ __launch_bounds__(128) void crf_final(
    float* __restrict__ outbuf,
    const void* __restrict__ tags,
    const int*  __restrict__ mask,
    const float* __restrict__ startT,
    const float* __restrict__ endT,
    const float* __restrict__ trans)
{
    const float* emis = outbuf + 1;
    const int b = blockIdx.x;
    const int tid = threadIdx.x;
    const float* em_b = emis + (size_t)b * SEQ * NT;
    const long long* t64 = (const long long*)tags;
    const int*       t32 = (const int*)tags;
    const int is64 = g_tags64;

    __shared__ float redf[128];
    __shared__ int   redi[128];
    __shared__ float Ms[81];
    __shared__ float s_num;

    // numerator (parallel over s) + mask count
    float acc = 0.0f;
    int   msum = 0;
    for (int s = tid; s < SEQ; s += 128) {
        int m = mask[b * SEQ + s];
        msum += m;
        if (s >= 1) {
            int tp  = is64 ? (int)t64[b * SEQ + s - 1] : t32[b * SEQ + s - 1];
            int tcu = is64 ? (int)t64[b * SEQ + s]     : t32[b * SEQ + s];
            acc += (float)m * (trans[tp * 9 + tcu] + em_b[s * NT + tcu]);
        }
    }
    redf[tid] = acc; redi[tid] = msum;
    __syncthreads();
    for (int o = 64; o > 0; o >>= 1) {
        if (tid < o) { redf[tid] += redf[tid + o]; redi[tid] += redi[tid + o]; }
        __syncthreads();
    }
    if (tid == 0) {
        int tg0  = is64 ? (int)t64[b * SEQ] : t32[b * SEQ];
        int last = redi[0] - 1;
        int tl   = is64 ? (int)t64[b * SEQ + last] : t32[b * SEQ + last];
        s_num = redf[0] + startT[tg0] + em_b[tg0] + endT[tl];
    }
    __syncthreads();

    // combine chunk matrices (warp 0, lanes 0..8 hold the score vector)
    if (tid < 32) {
        const int j = tid;
        float v = (j < 9) ? (startT[j] + em_b[j]) : -1e30f;
        for (int c = 0; c < CHUNKS; c++) {
            const float* Mc = g_M + (b * CHUNKS + c) * 81;
            for (int q = tid; q < 81; q += 32) Ms[q] = Mc[q];
            __syncwarp();
            float vals[9];
#pragma unroll
            for (int i2 = 0; i2 < 9; i2++) {
                float sv = __shfl_sync(0xffffffffu, v, i2);
                vals[i2] = sv + ((j < 9) ? Ms[i2 * 9 + j] : 0.0f);
            }
            float nv = -1e30f;
            if (j < 9) {
                float mx = vals[0];
#pragma unroll
                for (int i2 = 1; i2 < 9; i2++) mx = fmaxf(mx, vals[i2]);
                float s = 0.0f;
#pragma unroll
                for (int i2 = 0; i2 < 9; i2++) s += fast_ex2((vals[i2] - mx) * L2E);
                nv = fmaf(fast_lg2(s), LN2, mx);
            }
            __syncwarp();
            v = nv;
        }
        // denominator = logsumexp(v + end)
        float x = (j < 9) ? v + endT[j] : -1e30f;
        float mx = x;
#pragma unroll
        for (int o = 16; o > 0; o >>= 1) mx = fmaxf(mx, __shfl_xor_sync(0xffffffffu, mx, o));
        float e = (j < 9) ? fast_ex2((x - mx) * L2E) : 0.0f;
#pragma unroll
        for (int o = 16; o > 0; o >>= 1) e += __shfl_xor_sync(0xffffffffu, e, o);
        if (tid == 0) {
            float den = fmaf(fast_lg2(e), LN2, mx);
            atomicAdd(outbuf, s_num - den);
        }
    }
}

// ---------------------------------------------------------------------------
extern "C" void kernel_launch(void* const* d_in, const int* in_sizes, int n_in,
                              void* d_out, int out_size)
{
    const float* embed  = (const float*)d_in[0];
    const void*  tags   = d_in[1];
    const int*   mask   = (const int*)d_in[2];
    const float* W      = (const float*)d_in[3];
    const float* bias   = (const float*)d_in[4];
    const float* startT = (const float*)d_in[5];
    const float* endT   = (const float*)d_in[6];
    const float* trans  = (const float*)d_in[7];
    float* out = (float*)d_out;

    emis2<<<(BATCH * SEQ) / 64, 256>>>(embed, W, bias,
                                       (const unsigned*)tags, out);
    dim3 g2(CHUNKS, BATCH);
    crf_chunks2<<<g2, 96>>>(out, mask, trans);
    crf_final<<<BATCH, 128>>>(out, tags, mask, startT, endT, trans);
}